// round 1
// baseline (speedup 1.0000x reference)
#include <cuda_runtime.h>

#define NNODES 24
#define HID    64
#define OUTC   65
#define SMP    16          // samples per CTA
#define NP     (SMP/2)     // f32x2 sample pairs
#define SP     18          // padded sample stride (even -> 8B aligned rows)
#define NTHR   512
#define ROWS   (NNODES*OUTC)   // 1560 smem rows per buffer
#define BTOT   65536

typedef unsigned long long u64;

// packed fp32x2 FMA (Blackwell FFMA2 — only reachable via PTX fma.rn.f32x2)
__device__ __forceinline__ u64 ffma2(u64 a, u64 b, u64 c) {
    u64 d;
    asm("fma.rn.f32x2 %0, %1, %2, %3;" : "=l"(d) : "l"(a), "l"(b), "l"(c));
    return d;
}
// replicate a scalar float into both lanes of an f32x2 register
__device__ __forceinline__ u64 rep2(float x) {
    u64 d; unsigned xi = __float_as_uint(x);
    asm("mov.b64 %0, {%1, %1};" : "=l"(d) : "r"(xi));
    return d;
}

// SMPL skeleton adjacency, CSR (self + parent + children), 70 entries total
__constant__ int c_off[NNODES + 1] = {
    0,4,7,10,13,16,19,22,25,28,33,35,37,40,43,46,48,51,54,57,60,63,66,68,70};
__constant__ int c_nbr[70] = {
    0,1,2,3,   1,0,4,   2,0,5,   3,0,6,   4,1,7,   5,2,8,   6,3,9,
    7,4,10,    8,5,11,  9,6,12,13,14,     10,7,    11,8,    12,9,15,
    13,9,16,   14,9,17, 15,12,   16,13,18, 17,14,19, 18,16,20,
    19,17,21,  20,18,22, 21,19,23, 22,20,  23,21 };

template<int JW, bool RELU>
__device__ __forceinline__ void layer_step(
    const float* __restrict__ W,   // [24][64][JW]
    const float* __restrict__ AW,  // [24][24]
    const float* __restrict__ BI,  // [JW]
    float* __restrict__ act,       // smem [ROWS][SP] (input: l in 0..63)
    float* __restrict__ g,         // smem [ROWS][SP] (per-node GEMM out)
    int tid)
{
    const int ncols = NNODES * JW;

    // ---- per-node GEMM: g[k][j][s] = sum_l act[k][l][s] * W[k][l][j] ----
    for (int c = tid; c < ncols; c += NTHR) {
        const int k = c / JW;
        const int j = c - k * JW;
        const float* wcol = W + k * (HID * JW) + j;   // stride JW over l
        const float* arow = act + (k * OUTC) * SP;

        u64 acc[NP];
        #pragma unroll
        for (int p = 0; p < NP; ++p) acc[p] = 0ull;

        // split K into two halves to bound register live-range of wreg
        #pragma unroll 1
        for (int half = 0; half < 2; ++half) {
            const int lbase = half * 32;
            float wreg[32];
            #pragma unroll
            for (int l = 0; l < 32; ++l) wreg[l] = wcol[(lbase + l) * JW];
            #pragma unroll
            for (int l = 0; l < 32; ++l) {
                const u64 wp = rep2(wreg[l]);
                const u64* ap =
                    reinterpret_cast<const u64*>(arow + (lbase + l) * SP);
                #pragma unroll
                for (int p = 0; p < NP; ++p)
                    acc[p] = ffma2(wp, ap[p], acc[p]);   // uniform LDS.64 bcast
            }
        }
        u64* grow = reinterpret_cast<u64*>(g + (k * OUTC + j) * SP);
        #pragma unroll
        for (int p = 0; p < NP; ++p) grow[p] = acc[p];
    }
    __syncthreads();

    // ---- sparse adjacency mix + bias (+ReLU): act[k][j][s] = f(sum_m aw[k][m]*g[m][j][s] + b[j]) ----
    for (int c = tid; c < ncols; c += NTHR) {
        const int k = c / JW;
        const int j = c - k * JW;
        u64 r[NP];
        const u64 bp = rep2(BI[j]);
        #pragma unroll
        for (int p = 0; p < NP; ++p) r[p] = bp;

        const int e1 = c_off[k + 1];
        for (int e = c_off[k]; e < e1; ++e) {
            const int m = c_nbr[e];
            const u64 ap = rep2(AW[k * NNODES + m]);
            const u64* grow =
                reinterpret_cast<const u64*>(g + (m * OUTC + j) * SP);
            #pragma unroll
            for (int p = 0; p < NP; ++p)
                r[p] = ffma2(ap, grow[p], r[p]);
        }
        float* arow = act + (k * OUTC + j) * SP;
        #pragma unroll
        for (int p = 0; p < NP; ++p) {
            float2 v = *reinterpret_cast<float2*>(&r[p]);
            if (RELU) { v.x = fmaxf(v.x, 0.f); v.y = fmaxf(v.y, 0.f); }
            *reinterpret_cast<float2*>(arow + 2 * p) = v;
        }
    }
    __syncthreads();
}

extern __shared__ float smem_f[];

__global__ void __launch_bounds__(NTHR, 1) gnn_kernel(
    const float* __restrict__ x,
    const float* __restrict__ w0, const float* __restrict__ w1,
    const float* __restrict__ w2, const float* __restrict__ w3,
    const float* __restrict__ aw0, const float* __restrict__ aw1,
    const float* __restrict__ aw2, const float* __restrict__ aw3,
    const float* __restrict__ b0, const float* __restrict__ b1,
    const float* __restrict__ b2, const float* __restrict__ b3,
    float* __restrict__ out)
{
    float* act = smem_f;                 // [ROWS][SP]
    float* g   = smem_f + ROWS * SP;     // [ROWS][SP]
    const int tid = threadIdx.x;
    const size_t base = (size_t)blockIdx.x * SMP;

    // load x -> act (transposed to sample-minor), zero root joint (k==0)
    const float* xb = x + base * (NNODES * HID);
    for (int idx = tid; idx < SMP * NNODES * HID; idx += NTHR) {
        const int s = idx / (NNODES * HID);
        const int rr = idx - s * (NNODES * HID);       // rr = k*64 + l
        const float v = (rr < HID) ? 0.f
                                   : xb[(size_t)s * (NNODES * HID) + rr];
        const int k = rr >> 6, l = rr & (HID - 1);
        act[(k * OUTC + l) * SP + s] = v;
    }
    __syncthreads();

    layer_step<HID,  true >(w0, aw0, b0, act, g, tid);
    layer_step<HID,  true >(w1, aw1, b1, act, g, tid);
    layer_step<HID,  true >(w2, aw2, b2, act, g, tid);
    layer_step<OUTC, false>(w3, aw3, b3, act, g, tid);

    // write out [B][24][65], coalesced over the fused (k,j) index
    float* ob = out + base * ROWS;
    for (int idx = tid; idx < SMP * ROWS; idx += NTHR) {
        const int s = idx / ROWS;
        const int rr = idx - s * ROWS;
        ob[(size_t)s * ROWS + rr] = act[rr * SP + s];
    }
}

extern "C" void kernel_launch(void* const* d_in, const int* in_sizes, int n_in,
                              void* d_out, int out_size)
{
    (void)in_sizes; (void)n_in; (void)out_size;
    const float* x   = (const float*)d_in[0];
    const float* w0  = (const float*)d_in[1];
    const float* w1  = (const float*)d_in[2];
    const float* w2  = (const float*)d_in[3];
    const float* w3  = (const float*)d_in[4];
    const float* aw0 = (const float*)d_in[5];
    const float* aw1 = (const float*)d_in[6];
    const float* aw2 = (const float*)d_in[7];
    const float* aw3 = (const float*)d_in[8];
    const float* b0  = (const float*)d_in[9];
    const float* b1  = (const float*)d_in[10];
    const float* b2  = (const float*)d_in[11];
    const float* b3  = (const float*)d_in[12];
    float* out = (float*)d_out;

    const int smem_bytes = 2 * ROWS * SP * (int)sizeof(float);   // 224,640 B
    cudaFuncSetAttribute(gnn_kernel,
                         cudaFuncAttributeMaxDynamicSharedMemorySize,
                         smem_bytes);
    gnn_kernel<<<BTOT / SMP, NTHR, smem_bytes>>>(
        x, w0, w1, w2, w3, aw0, aw1, aw2, aw3, b0, b1, b2, b3, out);
}

// round 2
// speedup vs baseline: 1.0618x; 1.0618x over previous
#include <cuda_runtime.h>

#define NNODES 24
#define HID    64
#define OUTC   65
#define SMP    16          // samples per CTA
#define NP     (SMP/2)     // f32x2 sample pairs
#define SP     18          // padded sample stride (even -> 8B aligned rows)
#define NTHR   384
#define ROWS   (NNODES*OUTC)   // 1560 smem rows per buffer
#define BTOT   65536

typedef unsigned long long u64;

// packed fp32x2 FMA (Blackwell FFMA2 — only reachable via PTX fma.rn.f32x2)
__device__ __forceinline__ u64 ffma2(u64 a, u64 b, u64 c) {
    u64 d;
    asm("fma.rn.f32x2 %0, %1, %2, %3;" : "=l"(d) : "l"(a), "l"(b), "l"(c));
    return d;
}
__device__ __forceinline__ u64 rep2(float x) {
    u64 d; unsigned xi = __float_as_uint(x);
    asm("mov.b64 %0, {%1, %1};" : "=l"(d) : "r"(xi));
    return d;
}

// SMPL skeleton adjacency, CSR (self + parent + children), 70 entries total
__constant__ int c_off[NNODES + 1] = {
    0,4,7,10,13,16,19,22,25,28,33,35,37,40,43,46,48,51,54,57,60,63,66,68,70};
__constant__ int c_nbr[70] = {
    0,1,2,3,   1,0,4,   2,0,5,   3,0,6,   4,1,7,   5,2,8,   6,3,9,
    7,4,10,    8,5,11,  9,6,12,13,14,     10,7,    11,8,    12,9,15,
    13,9,16,   14,9,17, 15,12,   16,13,18, 17,14,19, 18,16,20,
    19,17,21,  20,18,22, 21,19,23, 22,20,  23,21 };

// runtime params staged into constant memory (async D2D memcpy at launch)
__constant__ float c_aw[4][NNODES * NNODES];
__constant__ float c_b[4][OUTC];

template<int JW, bool RELU>
__device__ __forceinline__ void layer_step(
    const float* __restrict__ W,   // [24][64][JW]
    int L,
    float* __restrict__ act,       // smem [ROWS][SP] (input: l in 0..63)
    float* __restrict__ g,         // smem [ROWS][SP]
    int tid)
{
    // ---- per-node GEMM, JBLK=4: 24 nodes x 16 j-groups == 384 threads ----
    {
        const int k  = tid >> 4;
        const int j0 = (tid & 15) << 2;
        const float* wbase = W + k * (HID * JW) + j0;
        const float* arow  = act + (k * OUTC) * SP;

        u64 acc0[NP], acc1[NP], acc2[NP], acc3[NP];
        #pragma unroll
        for (int p = 0; p < NP; ++p) { acc0[p]=0; acc1[p]=0; acc2[p]=0; acc3[p]=0; }

        #pragma unroll 1
        for (int lb = 0; lb < HID; lb += 8) {
            float wv[8][4];
            #pragma unroll
            for (int i = 0; i < 8; ++i) {
                if (JW == 64) {
                    float4 t = *reinterpret_cast<const float4*>(wbase + (lb + i) * JW);
                    wv[i][0] = t.x; wv[i][1] = t.y; wv[i][2] = t.z; wv[i][3] = t.w;
                } else {
                    #pragma unroll
                    for (int jj = 0; jj < 4; ++jj)
                        wv[i][jj] = wbase[(lb + i) * JW + jj];
                }
            }
            #pragma unroll
            for (int i = 0; i < 8; ++i) {
                const u64 w0 = rep2(wv[i][0]);
                const u64 w1 = rep2(wv[i][1]);
                const u64 w2 = rep2(wv[i][2]);
                const u64 w3 = rep2(wv[i][3]);
                const u64* ap = reinterpret_cast<const u64*>(arow + (lb + i) * SP);
                #pragma unroll
                for (int p = 0; p < NP; ++p) {
                    const u64 a = ap[p];
                    acc0[p] = ffma2(w0, a, acc0[p]);
                    acc1[p] = ffma2(w1, a, acc1[p]);
                    acc2[p] = ffma2(w2, a, acc2[p]);
                    acc3[p] = ffma2(w3, a, acc3[p]);
                }
            }
        }
        u64* g0 = reinterpret_cast<u64*>(g + (k * OUTC + j0 + 0) * SP);
        u64* g1 = reinterpret_cast<u64*>(g + (k * OUTC + j0 + 1) * SP);
        u64* g2 = reinterpret_cast<u64*>(g + (k * OUTC + j0 + 2) * SP);
        u64* g3 = reinterpret_cast<u64*>(g + (k * OUTC + j0 + 3) * SP);
        #pragma unroll
        for (int p = 0; p < NP; ++p) {
            g0[p] = acc0[p]; g1[p] = acc1[p]; g2[p] = acc2[p]; g3[p] = acc3[p];
        }
    }

    // tail column j=64 for the last layer (JW=65): one warp's worth of work
    if (JW == 65 && tid < NNODES) {
        const int k = tid;
        const float* wcol = W + k * (HID * JW) + 64;
        const float* arow = act + (k * OUTC) * SP;
        u64 acc[NP];
        #pragma unroll
        for (int p = 0; p < NP; ++p) acc[p] = 0;
        #pragma unroll 1
        for (int l = 0; l < HID; ++l) {
            const u64 wp = rep2(wcol[l * JW]);
            const u64* ap = reinterpret_cast<const u64*>(arow + l * SP);
            #pragma unroll
            for (int p = 0; p < NP; ++p)
                acc[p] = ffma2(wp, ap[p], acc[p]);
        }
        u64* grow = reinterpret_cast<u64*>(g + (k * OUTC + 64) * SP);
        #pragma unroll
        for (int p = 0; p < NP; ++p) grow[p] = acc[p];
    }
    __syncthreads();

    // ---- sparse adjacency mix + bias (+ReLU) ----
    const int ncols = NNODES * JW;
    for (int c = tid; c < ncols; c += NTHR) {
        const int k = c / JW;
        const int j = c - k * JW;
        u64 r[NP];
        const u64 bp = rep2(c_b[L][j]);
        #pragma unroll
        for (int p = 0; p < NP; ++p) r[p] = bp;

        const int e1 = c_off[k + 1];
        for (int e = c_off[k]; e < e1; ++e) {
            const int m = c_nbr[e];
            const u64 ap = rep2(c_aw[L][k * NNODES + m]);
            const u64* grow =
                reinterpret_cast<const u64*>(g + (m * OUTC + j) * SP);
            #pragma unroll
            for (int p = 0; p < NP; ++p)
                r[p] = ffma2(ap, grow[p], r[p]);
        }
        float* arow = act + (k * OUTC + j) * SP;
        #pragma unroll
        for (int p = 0; p < NP; ++p) {
            float2 v = *reinterpret_cast<float2*>(&r[p]);
            if (RELU) { v.x = fmaxf(v.x, 0.f); v.y = fmaxf(v.y, 0.f); }
            *reinterpret_cast<float2*>(arow + 2 * p) = v;
        }
    }
    __syncthreads();
}

extern __shared__ float smem_f[];

__global__ void __launch_bounds__(NTHR, 1) gnn_kernel(
    const float* __restrict__ x,
    const float* __restrict__ w0, const float* __restrict__ w1,
    const float* __restrict__ w2, const float* __restrict__ w3,
    float* __restrict__ out)
{
    float* act = smem_f;                 // [ROWS][SP]
    float* g   = smem_f + ROWS * SP;     // [ROWS][SP]
    const int tid = threadIdx.x;
    const size_t base = (size_t)blockIdx.x * SMP;

    // load x -> act (transposed to sample-minor), zero root joint (k==0)
    const float* xb = x + base * (NNODES * HID);
    for (int idx = tid; idx < SMP * NNODES * HID; idx += NTHR) {
        const int s = idx / (NNODES * HID);
        const int rr = idx - s * (NNODES * HID);       // rr = k*64 + l
        const float v = (rr < HID) ? 0.f
                                   : xb[(size_t)s * (NNODES * HID) + rr];
        const int k = rr >> 6, l = rr & (HID - 1);
        act[(k * OUTC + l) * SP + s] = v;
    }
    __syncthreads();

    layer_step<HID,  true >(w0, 0, act, g, tid);
    layer_step<HID,  true >(w1, 1, act, g, tid);
    layer_step<HID,  true >(w2, 2, act, g, tid);
    layer_step<OUTC, false>(w3, 3, act, g, tid);

    // write out [B][24][65], coalesced over the fused (k,j) index
    float* ob = out + base * ROWS;
    for (int idx = tid; idx < SMP * ROWS; idx += NTHR) {
        const int s = idx / ROWS;
        const int rr = idx - s * ROWS;
        ob[(size_t)s * ROWS + rr] = act[rr * SP + s];
    }
}

extern "C" void kernel_launch(void* const* d_in, const int* in_sizes, int n_in,
                              void* d_out, int out_size)
{
    (void)in_sizes; (void)n_in; (void)out_size;
    const float* x   = (const float*)d_in[0];
    const float* w0  = (const float*)d_in[1];
    const float* w1  = (const float*)d_in[2];
    const float* w2  = (const float*)d_in[3];
    const float* w3  = (const float*)d_in[4];
    float* out = (float*)d_out;

    // stage adjacency weights + biases into constant memory (D2D async,
    // graph-capturable; no allocations)
    const size_t awB = NNODES * NNODES * sizeof(float);
    cudaMemcpyToSymbolAsync(c_aw, d_in[5], awB, 0 * awB, cudaMemcpyDeviceToDevice, 0);
    cudaMemcpyToSymbolAsync(c_aw, d_in[6], awB, 1 * awB, cudaMemcpyDeviceToDevice, 0);
    cudaMemcpyToSymbolAsync(c_aw, d_in[7], awB, 2 * awB, cudaMemcpyDeviceToDevice, 0);
    cudaMemcpyToSymbolAsync(c_aw, d_in[8], awB, 3 * awB, cudaMemcpyDeviceToDevice, 0);
    const size_t brow = OUTC * sizeof(float);
    cudaMemcpyToSymbolAsync(c_b, d_in[9],  HID * sizeof(float), 0 * brow, cudaMemcpyDeviceToDevice, 0);
    cudaMemcpyToSymbolAsync(c_b, d_in[10], HID * sizeof(float), 1 * brow, cudaMemcpyDeviceToDevice, 0);
    cudaMemcpyToSymbolAsync(c_b, d_in[11], HID * sizeof(float), 2 * brow, cudaMemcpyDeviceToDevice, 0);
    cudaMemcpyToSymbolAsync(c_b, d_in[12], OUTC * sizeof(float), 3 * brow, cudaMemcpyDeviceToDevice, 0);

    const int smem_bytes = 2 * ROWS * SP * (int)sizeof(float);   // 224,640 B
    cudaFuncSetAttribute(gnn_kernel,
                         cudaFuncAttributeMaxDynamicSharedMemorySize,
                         smem_bytes);
    gnn_kernel<<<BTOT / SMP, NTHR, smem_bytes>>>(x, w0, w1, w2, w3, out);
}

// round 4
// speedup vs baseline: 1.1007x; 1.0366x over previous
#include <cuda_runtime.h>

#define NNODES 24
#define HID    64
#define OUTC   65
#define SMP    16          // samples per CTA
#define NP     (SMP/2)     // f32x2 sample pairs total
#define NPH    (NP/2)      // pairs per thread (sample-half split)
#define HOFF   (SMP/2)     // float offset of sample-half 1 within a row
#define SP     18          // padded sample stride (even -> 8B aligned rows)
#define NTHR   768
#define ROWS   (NNODES*OUTC)   // 1560 smem rows per buffer
#define BTOT   65536

typedef unsigned long long u64;

// packed fp32x2 FMA (Blackwell FFMA2 — only reachable via PTX fma.rn.f32x2)
__device__ __forceinline__ u64 ffma2(u64 a, u64 b, u64 c) {
    u64 d;
    asm("fma.rn.f32x2 %0, %1, %2, %3;" : "=l"(d) : "l"(a), "l"(b), "l"(c));
    return d;
}
__device__ __forceinline__ u64 rep2(float x) {
    u64 d; unsigned xi = __float_as_uint(x);
    asm("mov.b64 %0, {%1, %1};" : "=l"(d) : "r"(xi));
    return d;
}

// SMPL skeleton adjacency, CSR (self + parent + children), 70 entries total
__constant__ int c_off[NNODES + 1] = {
    0,4,7,10,13,16,19,22,25,28,33,35,37,40,43,46,48,51,54,57,60,63,66,68,70};
__constant__ int c_nbr[70] = {
    0,1,2,3,   1,0,4,   2,0,5,   3,0,6,   4,1,7,   5,2,8,   6,3,9,
    7,4,10,    8,5,11,  9,6,12,13,14,     10,7,    11,8,    12,9,15,
    13,9,16,   14,9,17, 15,12,   16,13,18, 17,14,19, 18,16,20,
    19,17,21,  20,18,22, 21,19,23, 22,20,  23,21 };

// runtime params staged into constant memory (async D2D memcpy at launch)
__constant__ float c_aw[4][NNODES * NNODES];
__constant__ float c_b[4][OUTC];

template<int JW, bool RELU>
__device__ __forceinline__ void layer_step(
    const float* __restrict__ W,   // [24][64][JW]
    int L,
    float* __restrict__ act,       // smem [ROWS][SP] (input: l in 0..63)
    float* __restrict__ g,         // smem [ROWS][SP]
    int tid)
{
    // ---- per-node GEMM, JBLK=4, sample-half split:
    //      384 units x 2 halves == 768 threads ----
    {
        const int half = (tid >= 384) ? 1 : 0;
        const int unit = tid - half * 384;
        const int k  = unit >> 4;
        const int j0 = (unit & 15) << 2;
        const int ho = half * HOFF;                       // +8 floats for half 1
        const float* wbase = W + k * (HID * JW) + j0;
        const float* arow  = act + (k * OUTC) * SP + ho;

        u64 acc0[NPH], acc1[NPH], acc2[NPH], acc3[NPH];
        #pragma unroll
        for (int p = 0; p < NPH; ++p) { acc0[p]=0; acc1[p]=0; acc2[p]=0; acc3[p]=0; }

        #pragma unroll 1
        for (int lb = 0; lb < HID; lb += 4) {
            float wv[4][4];
            #pragma unroll
            for (int i = 0; i < 4; ++i) {
                if (JW == 64) {
                    float4 t = *reinterpret_cast<const float4*>(wbase + (lb + i) * JW);
                    wv[i][0] = t.x; wv[i][1] = t.y; wv[i][2] = t.z; wv[i][3] = t.w;
                } else {
                    #pragma unroll
                    for (int jj = 0; jj < 4; ++jj)
                        wv[i][jj] = wbase[(lb + i) * JW + jj];
                }
            }
            #pragma unroll
            for (int i = 0; i < 4; ++i) {
                const u64 w0 = rep2(wv[i][0]);
                const u64 w1 = rep2(wv[i][1]);
                const u64 w2 = rep2(wv[i][2]);
                const u64 w3 = rep2(wv[i][3]);
                const u64* ap = reinterpret_cast<const u64*>(arow + (lb + i) * SP);
                #pragma unroll
                for (int p = 0; p < NPH; ++p) {
                    const u64 a = ap[p];
                    acc0[p] = ffma2(w0, a, acc0[p]);
                    acc1[p] = ffma2(w1, a, acc1[p]);
                    acc2[p] = ffma2(w2, a, acc2[p]);
                    acc3[p] = ffma2(w3, a, acc3[p]);
                }
            }
        }
        u64* g0 = reinterpret_cast<u64*>(g + (k * OUTC + j0 + 0) * SP + ho);
        u64* g1 = reinterpret_cast<u64*>(g + (k * OUTC + j0 + 1) * SP + ho);
        u64* g2 = reinterpret_cast<u64*>(g + (k * OUTC + j0 + 2) * SP + ho);
        u64* g3 = reinterpret_cast<u64*>(g + (k * OUTC + j0 + 3) * SP + ho);
        #pragma unroll
        for (int p = 0; p < NPH; ++p) {
            g0[p] = acc0[p]; g1[p] = acc1[p]; g2[p] = acc2[p]; g3[p] = acc3[p];
        }
    }

    // tail column j=64 for the last layer (JW=65): 48 threads
    if (JW == 65 && tid < 2 * NNODES) {
        const int k = tid >> 1;
        const int ho = (tid & 1) * HOFF;
        const float* wcol = W + k * (HID * JW) + 64;
        const float* arow = act + (k * OUTC) * SP + ho;
        u64 acc[NPH];
        #pragma unroll
        for (int p = 0; p < NPH; ++p) acc[p] = 0;
        #pragma unroll 1
        for (int l = 0; l < HID; ++l) {
            const u64 wp = rep2(wcol[l * JW]);
            const u64* ap = reinterpret_cast<const u64*>(arow + l * SP);
            #pragma unroll
            for (int p = 0; p < NPH; ++p)
                acc[p] = ffma2(wp, ap[p], acc[p]);
        }
        u64* grow = reinterpret_cast<u64*>(g + (k * OUTC + 64) * SP + ho);
        #pragma unroll
        for (int p = 0; p < NPH; ++p) grow[p] = acc[p];
    }
    __syncthreads();

    // ---- sparse adjacency mix + bias (+ReLU), full row per thread ----
    const int ncols = NNODES * JW;
    for (int c = tid; c < ncols; c += NTHR) {
        const int k = c / JW;
        const int j = c - k * JW;
        u64 r[NP];
        const u64 bp = rep2(c_b[L][j]);
        #pragma unroll
        for (int p = 0; p < NP; ++p) r[p] = bp;

        const int e1 = c_off[k + 1];
        for (int e = c_off[k]; e < e1; ++e) {
            const int m = c_nbr[e];
            const u64 ap = rep2(c_aw[L][k * NNODES + m]);
            const u64* grow =
                reinterpret_cast<const u64*>(g + (m * OUTC + j) * SP);
            #pragma unroll
            for (int p = 0; p < NP; ++p)
                r[p] = ffma2(ap, grow[p], r[p]);
        }
        float* arow = act + (k * OUTC + j) * SP;
        #pragma unroll
        for (int p = 0; p < NP; ++p) {
            float2 v = *reinterpret_cast<float2*>(&r[p]);
            if (RELU) { v.x = fmaxf(v.x, 0.f); v.y = fmaxf(v.y, 0.f); }
            *reinterpret_cast<float2*>(arow + 2 * p) = v;
        }
    }
    __syncthreads();
}

extern __shared__ float smem_f[];

__global__ void __launch_bounds__(NTHR, 1) gnn_kernel(
    const float* __restrict__ x,
    const float* __restrict__ w0, const float* __restrict__ w1,
    const float* __restrict__ w2, const float* __restrict__ w3,
    float* __restrict__ out)
{
    float* act = smem_f;                 // [ROWS][SP]
    float* g   = smem_f + ROWS * SP;     // [ROWS][SP]
    const int tid = threadIdx.x;
    const size_t base = (size_t)blockIdx.x * SMP;

    // load x -> act (transposed to sample-minor), zero root joint (k==0)
    const float* xb = x + base * (NNODES * HID);
    for (int idx = tid; idx < SMP * NNODES * HID; idx += NTHR) {
        const int s = idx / (NNODES * HID);
        const int rr = idx - s * (NNODES * HID);       // rr = k*64 + l
        const float v = (rr < HID) ? 0.f
                                   : xb[(size_t)s * (NNODES * HID) + rr];
        const int k = rr >> 6, l = rr & (HID - 1);
        act[(k * OUTC + l) * SP + s] = v;
    }
    __syncthreads();

    layer_step<HID,  true >(w0, 0, act, g, tid);
    layer_step<HID,  true >(w1, 1, act, g, tid);
    layer_step<HID,  true >(w2, 2, act, g, tid);
    layer_step<OUTC, false>(w3, 3, act, g, tid);

    // write out [B][24][65], coalesced over the fused (k,j) index
    float* ob = out + base * ROWS;
    for (int idx = tid; idx < SMP * ROWS; idx += NTHR) {
        const int s = idx / ROWS;
        const int rr = idx - s * ROWS;
        ob[(size_t)s * ROWS + rr] = act[rr * SP + s];
    }
}

extern "C" void kernel_launch(void* const* d_in, const int* in_sizes, int n_in,
                              void* d_out, int out_size)
{
    (void)in_sizes; (void)n_in; (void)out_size;
    const float* x   = (const float*)d_in[0];
    const float* w0  = (const float*)d_in[1];
    const float* w1  = (const float*)d_in[2];
    const float* w2  = (const float*)d_in[3];
    const float* w3  = (const float*)d_in[4];
    float* out = (float*)d_out;

    // stage adjacency weights + biases into constant memory (D2D async,
    // graph-capturable; no allocations)
    const size_t awB = NNODES * NNODES * sizeof(float);
    cudaMemcpyToSymbolAsync(c_aw, d_in[5], awB, 0 * awB, cudaMemcpyDeviceToDevice, 0);
    cudaMemcpyToSymbolAsync(c_aw, d_in[6], awB, 1 * awB, cudaMemcpyDeviceToDevice, 0);
    cudaMemcpyToSymbolAsync(c_aw, d_in[7], awB, 2 * awB, cudaMemcpyDeviceToDevice, 0);
    cudaMemcpyToSymbolAsync(c_aw, d_in[8], awB, 3 * awB, cudaMemcpyDeviceToDevice, 0);
    const size_t brow = OUTC * sizeof(float);
    cudaMemcpyToSymbolAsync(c_b, d_in[9],  HID * sizeof(float), 0 * brow, cudaMemcpyDeviceToDevice, 0);
    cudaMemcpyToSymbolAsync(c_b, d_in[10], HID * sizeof(float), 1 * brow, cudaMemcpyDeviceToDevice, 0);
    cudaMemcpyToSymbolAsync(c_b, d_in[11], HID * sizeof(float), 2 * brow, cudaMemcpyDeviceToDevice, 0);
    cudaMemcpyToSymbolAsync(c_b, d_in[12], OUTC * sizeof(float), 3 * brow, cudaMemcpyDeviceToDevice, 0);

    const int smem_bytes = 2 * ROWS * SP * (int)sizeof(float);   // 224,640 B
    cudaFuncSetAttribute(gnn_kernel,
                         cudaFuncAttributeMaxDynamicSharedMemorySize,
                         smem_bytes);
    gnn_kernel<<<BTOT / SMP, NTHR, smem_bytes>>>(x, w0, w1, w2, w3, out);
}